// round 1
// baseline (speedup 1.0000x reference)
#include <cuda_runtime.h>

#define NEG_SLOPE 0.2f
#define MAXN 100000

// ---- scratch (static __device__ arrays; no allocation anywhere) ----
__device__ __align__(16) float g_h0 [MAXN];
__device__ __align__(16) float g_p1 [MAXN * 16];   // layer1 packed per (node,head): {S, den}
__device__ __align__(16) float g_h2 [MAXN * 16];
__device__ __align__(16) float g_als2[MAXN * 4];
__device__ __align__(16) float g_ald2[MAXN * 4];
__device__ __align__(16) float g_num2[MAXN * 16];
__device__ __align__(16) float g_den2[MAXN * 4];
__device__ __align__(16) float g_h3 [MAXN * 8];
__device__ __align__(16) float g_als3[MAXN * 2];
__device__ __align__(16) float g_ald3[MAXN * 2];
__device__ __align__(16) float g_num3[MAXN * 8];
__device__ __align__(16) float g_den3[MAXN * 2];
__device__ __align__(16) float g_x6 [MAXN * 8];
__device__ __align__(16) float g_r3 [MAXN * 8];
__device__ __align__(16) float g_ld [MAXN * 2];    // {dot_sum, deg}
__device__ __align__(16) float g_ka [16];          // layer1 head consts: kas[8], kad[8]

__device__ __forceinline__ float lrelu(float x) { return x > 0.f ? x : NEG_SLOPE * x; }

__device__ __forceinline__ void red4(float* p, float a, float b, float c, float d) {
    asm volatile("red.global.add.v4.f32 [%0], {%1,%2,%3,%4};"
                 :: "l"(p), "f"(a), "f"(b), "f"(c), "f"(d) : "memory");
}
__device__ __forceinline__ void red2(float* p, float a, float b) {
    asm volatile("red.global.add.v2.f32 [%0], {%1,%2};"
                 :: "l"(p), "f"(a), "f"(b) : "memory");
}

// ---------- K0: h0 = relu(x1@lin1w^T + b); layer1 self-term init; ka consts ----------
__global__ void k_node0(const float* __restrict__ x1,
                        const float* __restrict__ lin1w, const float* __restrict__ lin1b,
                        const float* __restrict__ W1,
                        const float* __restrict__ as1, const float* __restrict__ ad1,
                        int N)
{
    int n = blockIdx.x * blockDim.x + threadIdx.x;
    if (n >= N) return;
    if (n == 0) {
        #pragma unroll
        for (int h = 0; h < 8; h++) {
            float kas = 0.f, kad = 0.f;
            #pragma unroll
            for (int c = 0; c < 4; c++) {
                float w = W1[h * 4 + c];
                kas = fmaf(w, as1[h * 4 + c], kas);
                kad = fmaf(w, ad1[h * 4 + c], kad);
            }
            g_ka[h] = kas; g_ka[8 + h] = kad;
        }
    }
    float h0 = __ldg(&lin1b[0]);
    #pragma unroll
    for (int i = 0; i < 7; i++) h0 = fmaf(__ldg(&x1[n * 7 + i]), __ldg(&lin1w[i]), h0);
    h0 = fmaxf(h0, 0.f);
    g_h0[n] = h0;
    #pragma unroll
    for (int h = 0; h < 8; h++) {
        float kas = 0.f, kad = 0.f;
        #pragma unroll
        for (int c = 0; c < 4; c++) {
            float w = __ldg(&W1[h * 4 + c]);
            kas = fmaf(w, __ldg(&as1[h * 4 + c]), kas);
            kad = fmaf(w, __ldg(&ad1[h * 4 + c]), kad);
        }
        float ws = __expf(lrelu(h0 * (kas + kad)));
        g_p1[n * 16 + h * 2]     = ws * h0;  // S (self term)
        g_p1[n * 16 + h * 2 + 1] = ws;       // den (self term)
    }
}

// ---------- K1: layer1 edge scatter (rank-1): per edge 4 v4 reds ----------
__global__ void k_edge1(const int* __restrict__ ei, int E)
{
    int e = blockIdx.x * blockDim.x + threadIdx.x;
    if (e >= E) return;
    int s = __ldg(&ei[e]);
    int d = __ldg(&ei[E + e]);
    if (s == d) return;
    float h0s = __ldg(&g_h0[s]);
    float h0d = __ldg(&g_h0[d]);
    float4 kas0 = *(const float4*)&g_ka[0];
    float4 kas1 = *(const float4*)&g_ka[4];
    float4 kad0 = *(const float4*)&g_ka[8];
    float4 kad1 = *(const float4*)&g_ka[12];
    float w0 = __expf(lrelu(fmaf(h0s, kas0.x, h0d * kad0.x)));
    float w1 = __expf(lrelu(fmaf(h0s, kas0.y, h0d * kad0.y)));
    float w2 = __expf(lrelu(fmaf(h0s, kas0.z, h0d * kad0.z)));
    float w3 = __expf(lrelu(fmaf(h0s, kas0.w, h0d * kad0.w)));
    float w4 = __expf(lrelu(fmaf(h0s, kas1.x, h0d * kad1.x)));
    float w5 = __expf(lrelu(fmaf(h0s, kas1.y, h0d * kad1.y)));
    float w6 = __expf(lrelu(fmaf(h0s, kas1.z, h0d * kad1.z)));
    float w7 = __expf(lrelu(fmaf(h0s, kas1.w, h0d * kad1.w)));
    float* base = g_p1 + (size_t)d * 16;
    red4(base,      w0 * h0s, w0, w1 * h0s, w1);
    red4(base + 4,  w2 * h0s, w2, w3 * h0s, w3);
    red4(base + 8,  w4 * h0s, w4, w5 * h0s, w5);
    red4(base + 12, w6 * h0s, w6, w7 * h0s, w7);
}

// ---------- K2: x3 = relu(GAT1 out + b1); prep layer2 (h2, al2, self init) ----------
__global__ void k_node2(const float* __restrict__ W1, const float* __restrict__ b1,
                        const float* __restrict__ W2,
                        const float* __restrict__ as2, const float* __restrict__ ad2,
                        int N)
{
    int n = blockIdx.x * blockDim.x + threadIdx.x;
    if (n >= N) return;
    float x3[32];
    #pragma unroll
    for (int h = 0; h < 8; h++) {
        float S   = g_p1[n * 16 + h * 2];
        float den = g_p1[n * 16 + h * 2 + 1];
        float r = S / den;
        #pragma unroll
        for (int c = 0; c < 4; c++)
            x3[h * 4 + c] = fmaxf(fmaf(r, __ldg(&W1[h * 4 + c]), __ldg(&b1[h * 4 + c])), 0.f);
    }
    float h2[16];
    #pragma unroll
    for (int j = 0; j < 16; j++) h2[j] = 0.f;
    #pragma unroll
    for (int i = 0; i < 32; i++) {
        float xi = x3[i];
        #pragma unroll
        for (int j = 0; j < 16; j++) h2[j] = fmaf(xi, __ldg(&W2[i * 16 + j]), h2[j]);
    }
    #pragma unroll
    for (int q = 0; q < 4; q++)
        *(float4*)&g_h2[n * 16 + q * 4] = make_float4(h2[q*4], h2[q*4+1], h2[q*4+2], h2[q*4+3]);
    #pragma unroll
    for (int h = 0; h < 4; h++) {
        float als = 0.f, ald = 0.f;
        #pragma unroll
        for (int c = 0; c < 4; c++) {
            als = fmaf(h2[h * 4 + c], __ldg(&as2[h * 4 + c]), als);
            ald = fmaf(h2[h * 4 + c], __ldg(&ad2[h * 4 + c]), ald);
        }
        g_als2[n * 4 + h] = als;
        g_ald2[n * 4 + h] = ald;
        float ws = __expf(lrelu(als + ald));
        g_den2[n * 4 + h] = ws;
        #pragma unroll
        for (int c = 0; c < 4; c++) g_num2[n * 16 + h * 4 + c] = ws * h2[h * 4 + c];
    }
}

// ---------- K3: layer2 edge scatter: 5 v4 reds/edge ----------
__global__ void k_edge2(const int* __restrict__ ei, int E)
{
    int e = blockIdx.x * blockDim.x + threadIdx.x;
    if (e >= E) return;
    int s = __ldg(&ei[e]);
    int d = __ldg(&ei[E + e]);
    if (s == d) return;
    float4 as = __ldg((const float4*)&g_als2[(size_t)s * 4]);
    float4 ad = __ldg((const float4*)&g_ald2[(size_t)d * 4]);
    float w0 = __expf(lrelu(as.x + ad.x));
    float w1 = __expf(lrelu(as.y + ad.y));
    float w2 = __expf(lrelu(as.z + ad.z));
    float w3 = __expf(lrelu(as.w + ad.w));
    red4(g_den2 + (size_t)d * 4, w0, w1, w2, w3);
    const float4* hp = (const float4*)&g_h2[(size_t)s * 16];
    float* nb = g_num2 + (size_t)d * 16;
    float4 h;
    h = __ldg(hp + 0); red4(nb + 0,  w0 * h.x, w0 * h.y, w0 * h.z, w0 * h.w);
    h = __ldg(hp + 1); red4(nb + 4,  w1 * h.x, w1 * h.y, w1 * h.z, w1 * h.w);
    h = __ldg(hp + 2); red4(nb + 8,  w2 * h.x, w2 * h.y, w2 * h.z, w2 * h.w);
    h = __ldg(hp + 3); red4(nb + 12, w3 * h.x, w3 * h.y, w3 * h.z, w3 * h.w);
}

// ---------- K4: x4 = relu(GAT2 out + b2); prep layer3 ----------
__global__ void k_node3(const float* __restrict__ b2, const float* __restrict__ W3,
                        const float* __restrict__ as3, const float* __restrict__ ad3,
                        int N)
{
    int n = blockIdx.x * blockDim.x + threadIdx.x;
    if (n >= N) return;
    float x4[16];
    #pragma unroll
    for (int h = 0; h < 4; h++) {
        float inv = 1.f / g_den2[n * 4 + h];
        #pragma unroll
        for (int c = 0; c < 4; c++)
            x4[h * 4 + c] = fmaxf(fmaf(g_num2[n * 16 + h * 4 + c], inv, __ldg(&b2[h * 4 + c])), 0.f);
    }
    float h3[8];
    #pragma unroll
    for (int k = 0; k < 8; k++) h3[k] = 0.f;
    #pragma unroll
    for (int j = 0; j < 16; j++) {
        float xj = x4[j];
        #pragma unroll
        for (int k = 0; k < 8; k++) h3[k] = fmaf(xj, __ldg(&W3[j * 8 + k]), h3[k]);
    }
    *(float4*)&g_h3[n * 8]     = make_float4(h3[0], h3[1], h3[2], h3[3]);
    *(float4*)&g_h3[n * 8 + 4] = make_float4(h3[4], h3[5], h3[6], h3[7]);
    #pragma unroll
    for (int h = 0; h < 2; h++) {
        float als = 0.f, ald = 0.f;
        #pragma unroll
        for (int c = 0; c < 4; c++) {
            als = fmaf(h3[h * 4 + c], __ldg(&as3[h * 4 + c]), als);
            ald = fmaf(h3[h * 4 + c], __ldg(&ad3[h * 4 + c]), ald);
        }
        g_als3[n * 2 + h] = als;
        g_ald3[n * 2 + h] = ald;
        float ws = __expf(lrelu(als + ald));
        g_den3[n * 2 + h] = ws;
        #pragma unroll
        for (int c = 0; c < 4; c++) g_num3[n * 8 + h * 4 + c] = ws * h3[h * 4 + c];
    }
}

// ---------- K5: layer3 edge scatter: 2 v4 + 1 v2 reds/edge ----------
__global__ void k_edge3(const int* __restrict__ ei, int E)
{
    int e = blockIdx.x * blockDim.x + threadIdx.x;
    if (e >= E) return;
    int s = __ldg(&ei[e]);
    int d = __ldg(&ei[E + e]);
    if (s == d) return;
    float2 as = __ldg((const float2*)&g_als3[(size_t)s * 2]);
    float2 ad = __ldg((const float2*)&g_ald3[(size_t)d * 2]);
    float w0 = __expf(lrelu(as.x + ad.x));
    float w1 = __expf(lrelu(as.y + ad.y));
    red2(g_den3 + (size_t)d * 2, w0, w1);
    float4 lo = __ldg((const float4*)&g_h3[(size_t)s * 8]);
    float4 hi = __ldg((const float4*)&g_h3[(size_t)s * 8 + 4]);
    red4(g_num3 + (size_t)d * 8,     w0 * lo.x, w0 * lo.y, w0 * lo.z, w0 * lo.w);
    red4(g_num3 + (size_t)d * 8 + 4, w1 * hi.x, w1 * hi.y, w1 * hi.z, w1 * hi.w);
}

// ---------- K6: x6 = relu(GAT3 out + b3); init scoring accumulators ----------
__global__ void k_node4(const float* __restrict__ b3, int N)
{
    int n = blockIdx.x * blockDim.x + threadIdx.x;
    if (n >= N) return;
    float x6[8];
    float inv0 = 1.f / g_den3[n * 2];
    float inv1 = 1.f / g_den3[n * 2 + 1];
    #pragma unroll
    for (int k = 0; k < 8; k++) {
        float inv = (k < 4) ? inv0 : inv1;
        x6[k] = fmaxf(fmaf(g_num3[n * 8 + k], inv, __ldg(&b3[k])), 0.f);
    }
    *(float4*)&g_x6[n * 8]     = make_float4(x6[0], x6[1], x6[2], x6[3]);
    *(float4*)&g_x6[n * 8 + 4] = make_float4(x6[4], x6[5], x6[6], x6[7]);
    *(float4*)&g_r3[n * 8]     = make_float4(x6[0], x6[1], x6[2], x6[3]);  // self term
    *(float4*)&g_r3[n * 8 + 4] = make_float4(x6[4], x6[5], x6[6], x6[7]);
    float dot = 0.f;
    #pragma unroll
    for (int k = 0; k < 8; k++) dot = fmaf(x6[k], x6[k], dot);
    g_ld[n * 2]     = dot;   // local numerator (self x6.x6)
    g_ld[n * 2 + 1] = 1.f;   // deg (self)
}

// ---------- K7: final scoring edge pass (segment by src): 2 v4 + 1 v2 reds/edge ----------
__global__ void k_edgeF(const int* __restrict__ ei, int E)
{
    int e = blockIdx.x * blockDim.x + threadIdx.x;
    if (e >= E) return;
    int s = __ldg(&ei[e]);
    int d = __ldg(&ei[E + e]);
    if (s == d) return;
    float4 a0 = __ldg((const float4*)&g_x6[(size_t)s * 8]);
    float4 a1 = __ldg((const float4*)&g_x6[(size_t)s * 8 + 4]);
    float4 b0 = __ldg((const float4*)&g_x6[(size_t)d * 8]);
    float4 b1 = __ldg((const float4*)&g_x6[(size_t)d * 8 + 4]);
    float dot = a0.x * b0.x + a0.y * b0.y + a0.z * b0.z + a0.w * b0.w
              + a1.x * b1.x + a1.y * b1.y + a1.z * b1.z + a1.w * b1.w;
    red2(g_ld + (size_t)s * 2, dot, 1.f);
    red4(g_r3 + (size_t)s * 8,     b0.x, b0.y, b0.z, b0.w);
    red4(g_r3 + (size_t)s * 8 + 4, b1.x, b1.y, b1.z, b1.w);
}

// ---------- K8: out = local + (R3 @ lin2_w^T) ----------
__global__ void k_out(const float* __restrict__ lin2w, float* __restrict__ out, int N)
{
    int n = blockIdx.x * blockDim.x + threadIdx.x;
    if (n >= N) return;
    float deg = g_ld[n * 2 + 1];
    float inv = 1.f / deg;
    float local = g_ld[n * 2] * inv;
    float r = 0.f;
    #pragma unroll
    for (int c = 0; c < 8; c++) r = fmaf(g_r3[n * 8 + c], __ldg(&lin2w[c]), r);
    out[n] = local + r * inv;
}

extern "C" void kernel_launch(void* const* d_in, const int* in_sizes, int n_in,
                              void* d_out, int out_size)
{
    const float* x1 = (const float*)d_in[0];
    const int*   ei = (const int*)d_in[2];
    // num_nodes may or may not be materialized as input #3; detect by size.
    int wb = (in_sizes[3] == 7) ? 3 : 4;
    const float* lin1w = (const float*)d_in[wb + 0];
    const float* lin1b = (const float*)d_in[wb + 1];
    const float* lin2w = (const float*)d_in[wb + 2];
    const float* W1    = (const float*)d_in[wb + 3];
    const float* as1   = (const float*)d_in[wb + 4];
    const float* ad1   = (const float*)d_in[wb + 5];
    const float* b1    = (const float*)d_in[wb + 6];
    const float* W2    = (const float*)d_in[wb + 7];
    const float* as2   = (const float*)d_in[wb + 8];
    const float* ad2   = (const float*)d_in[wb + 9];
    const float* b2    = (const float*)d_in[wb + 10];
    const float* W3    = (const float*)d_in[wb + 11];
    const float* as3   = (const float*)d_in[wb + 12];
    const float* ad3   = (const float*)d_in[wb + 13];
    const float* b3    = (const float*)d_in[wb + 14];

    int N = in_sizes[0] / 7;
    int E = in_sizes[2] / 2;
    int nb = (N + 255) / 256;
    int eb = (E + 255) / 256;

    k_node0<<<nb, 256>>>(x1, lin1w, lin1b, W1, as1, ad1, N);
    k_edge1<<<eb, 256>>>(ei, E);
    k_node2<<<nb, 256>>>(W1, b1, W2, as2, ad2, N);
    k_edge2<<<eb, 256>>>(ei, E);
    k_node3<<<nb, 256>>>(b2, W3, as3, ad3, N);
    k_edge3<<<eb, 256>>>(ei, E);
    k_node4<<<nb, 256>>>(b3, N);
    k_edgeF<<<eb, 256>>>(ei, E);
    k_out<<<nb, 256>>>(lin2w, (float*)d_out, N);
}